// round 2
// baseline (speedup 1.0000x reference)
#include <cuda_runtime.h>

#define NN 500000
#define NE 8000000
#define NG 1024

// Scratch (static __device__ — no allocations allowed)
__device__ int    g_is64;
__device__ float  g_deg[NN];
__device__ float  g_dinv[NN];
__device__ float2 g_q1[NN];
__device__ float2 g_S1[NN];
__device__ float4 g_q2[NN * 4];   // 16 floats/node = dinv * relu(y@W1+b1)
__device__ float4 g_S2[NN * 4];
__device__ float  g_psum[NG];
__device__ float  g_pcnt[NG];

// Load index element i from a buffer that is either int64 or int32.
__device__ __forceinline__ int ld_idx(const void* p, long long i) {
    if (g_is64) return (int)((const long long*)p)[i];
    return ((const int*)p)[i];
}

__global__ void k_init() {
    int i = blockIdx.x * blockDim.x + threadIdx.x;
    if (i == 0) g_is64 = 1;
    if (i < NN) g_deg[i] = 1.0f;          // self loop
    if (i < NG) { g_psum[i] = 0.0f; g_pcnt[i] = 0.0f; }
}

// Probe first 256 words as int64: node ids are in [0, NN), so int32 data
// reinterpreted as int64 yields out-of-range values with probability ~1.
__global__ void k_detect(const void* ei) {
    const long long* p = (const long long*)ei;
    long long v = p[threadIdx.x];         // 2 KB read, in bounds either way
    if (v < 0 || v >= NN) atomicAnd(&g_is64, 0);
}

__global__ void k_degree(const void* __restrict__ ei) {
    int e = blockIdx.x * blockDim.x + threadIdx.x;
    if (e < NE) {
        int t = ld_idx(ei, (long long)NE + e);
        atomicAdd(&g_deg[t], 1.0f);
    }
}

__global__ void k_prep1(const float* __restrict__ x) {
    int i = blockIdx.x * blockDim.x + threadIdx.x;
    if (i >= NN) return;
    float d = rsqrtf(g_deg[i]);           // deg >= 1 always (self loop)
    g_dinv[i] = d;
    float2 xv = ((const float2*)x)[i];
    float2 q = make_float2(d * xv.x, d * xv.y);
    g_q1[i] = q;
    g_S1[i] = q;                          // self-loop contribution
}

__global__ void k_edge1(const void* __restrict__ ei) {
    int e = blockIdx.x * blockDim.x + threadIdx.x;
    if (e >= NE) return;
    int s = ld_idx(ei, e);
    int t = ld_idx(ei, (long long)NE + e);
    float2 v = g_q1[s];
    atomicAdd(&g_S1[t], v);               // red.global.v2.f32 (sm_90+)
}

__global__ void k_mid(const float* __restrict__ W1, const float* __restrict__ b1) {
    int i = blockIdx.x * blockDim.x + threadIdx.x;
    if (i >= NN) return;
    float d = g_dinv[i];
    float2 Sv = g_S1[i];
    float yx = d * Sv.x;
    float yy = d * Sv.y;
#pragma unroll
    for (int c = 0; c < 4; c++) {
        float4 w0 = ((const float4*)W1)[c];          // W1 row 0
        float4 w1 = ((const float4*)(W1 + 16))[c];   // W1 row 1
        float4 bb = ((const float4*)b1)[c];
        float4 h;
        h.x = d * fmaxf(fmaf(yx, w0.x, fmaf(yy, w1.x, bb.x)), 0.0f);
        h.y = d * fmaxf(fmaf(yx, w0.y, fmaf(yy, w1.y, bb.y)), 0.0f);
        h.z = d * fmaxf(fmaf(yx, w0.z, fmaf(yy, w1.z, bb.z)), 0.0f);
        h.w = d * fmaxf(fmaf(yx, w0.w, fmaf(yy, w1.w, bb.w)), 0.0f);
        g_q2[i * 4 + c] = h;
        g_S2[i * 4 + c] = h;              // self loop
    }
}

// 4 threads per edge: each handles one float4 chunk -> contiguous 64B per edge
__global__ void k_edge2(const void* __restrict__ ei) {
    long long tid = (long long)blockIdx.x * blockDim.x + threadIdx.x;
    long long e = tid >> 2;
    int p = (int)(tid & 3);
    if (e >= NE) return;
    int s = ld_idx(ei, e);
    int t = ld_idx(ei, (long long)NE + e);
    float4 v = g_q2[(long long)s * 4 + p];
    atomicAdd(&g_S2[(long long)t * 4 + p], v);   // red.global.v4.f32
}

__global__ void k_pool(const void* __restrict__ batch,
                       const float* __restrict__ W2, const float* __restrict__ b2,
                       const float* __restrict__ Wl) {
    __shared__ float sW2[16 * 32];
    __shared__ float sb2[32];
    __shared__ float sWl[32];
    for (int j = threadIdx.x; j < 512; j += blockDim.x) sW2[j] = W2[j];
    if (threadIdx.x < 32) { sb2[threadIdx.x] = b2[threadIdx.x]; sWl[threadIdx.x] = Wl[threadIdx.x]; }
    __syncthreads();

    int i = blockIdx.x * blockDim.x + threadIdx.x;
    float val = 0.0f;
    int g = -1;
    if (i < NN) {
        float d = g_dinv[i];
        float z[16];
#pragma unroll
        for (int c = 0; c < 4; c++) {
            float4 v = g_S2[(long long)i * 4 + c];
            z[4 * c + 0] = d * v.x;
            z[4 * c + 1] = d * v.y;
            z[4 * c + 2] = d * v.z;
            z[4 * c + 3] = d * v.w;
        }
        float s = 0.0f;
#pragma unroll
        for (int k = 0; k < 32; k++) {
            float acc = sb2[k];
#pragma unroll
            for (int j = 0; j < 16; j++) acc = fmaf(z[j], sW2[j * 32 + k], acc);
            s = fmaf(fmaxf(acc, 0.0f), sWl[k], s);
        }
        val = s;
        g = ld_idx(batch, i);
    }

    // batch is sorted -> contiguous equal-g runs. Segmented warp reduction to
    // avoid ~500k same-address global atomics.
    float cnt = (g >= 0) ? 1.0f : 0.0f;
    const unsigned full = 0xffffffffu;
    int lane = threadIdx.x & 31;
#pragma unroll
    for (int off = 1; off < 32; off <<= 1) {
        float vo = __shfl_down_sync(full, val, off);
        float co = __shfl_down_sync(full, cnt, off);
        int   go = __shfl_down_sync(full, g,   off);
        if (lane + off < 32 && go == g) { val += vo; cnt += co; }
    }
    int gup = __shfl_up_sync(full, g, 1);
    if (g >= 0 && (lane == 0 || gup != g)) {
        atomicAdd(&g_psum[g], val);
        atomicAdd(&g_pcnt[g], cnt);
    }
}

__global__ void k_out(float* __restrict__ out, const float* __restrict__ bl) {
    int g = blockIdx.x * blockDim.x + threadIdx.x;
    if (g < NG) out[g] = g_psum[g] / fmaxf(g_pcnt[g], 1.0f) + bl[0];
}

extern "C" void kernel_launch(void* const* d_in, const int* in_sizes, int n_in,
                              void* d_out, int out_size) {
    const float* x     = (const float*)d_in[0];
    const void*  ei    = d_in[1];
    const void*  batch = d_in[2];
    const float* W1    = (const float*)d_in[3];
    const float* b1    = (const float*)d_in[4];
    const float* W2    = (const float*)d_in[5];
    const float* b2    = (const float*)d_in[6];
    const float* Wl    = (const float*)d_in[7];
    const float* bl    = (const float*)d_in[8];
    float* out = (float*)d_out;

    const int TB = 256;
    k_init  <<<(NN + TB - 1) / TB, TB>>>();
    k_detect<<<1, 256>>>(ei);
    k_degree<<<(NE + TB - 1) / TB, TB>>>(ei);
    k_prep1 <<<(NN + TB - 1) / TB, TB>>>(x);
    k_edge1 <<<(NE + TB - 1) / TB, TB>>>(ei);
    k_mid   <<<(NN + TB - 1) / TB, TB>>>(W1, b1);
    k_edge2 <<<(int)(((long long)NE * 4 + TB - 1) / TB), TB>>>(ei);
    k_pool  <<<(NN + TB - 1) / TB, TB>>>(batch, W2, b2, Wl);
    k_out   <<<(NG + TB - 1) / TB, TB>>>(out, bl);
}

// round 3
// speedup vs baseline: 1.2180x; 1.2180x over previous
#include <cuda_runtime.h>
#include <cuda_fp16.h>

#define NN 500000
#define NE 8000000
#define NG 1024

// Scratch (static __device__ — no allocations allowed)
__device__ int    g_is64;
__device__ float  g_deg[NN];
__device__ float  g_dinv[NN];
__device__ float2 g_q1[NN];
__device__ float2 g_S1[NN];
__device__ uint4  g_q2h[NN * 2];   // 16 fp16 per node = dinv * relu(y@W1+b1), packed
__device__ uint4  g_S2h[NN * 2];   // fp16 accumulator
__device__ float  g_psum[NG];
__device__ float  g_pcnt[NG];

// Load index element i from a buffer that is either int64 or int32.
__device__ __forceinline__ int ld_idx(const void* p, long long i) {
    if (g_is64) return (int)((const long long*)p)[i];
    return ((const int*)p)[i];
}

__global__ void k_init() {
    int i = blockIdx.x * blockDim.x + threadIdx.x;
    if (i == 0) g_is64 = 1;
    if (i < NN) g_deg[i] = 1.0f;          // self loop
    if (i < NG) { g_psum[i] = 0.0f; g_pcnt[i] = 0.0f; }
}

// Probe first 256 words as int64: node ids are in [0, NN), so int32 data
// reinterpreted as int64 yields out-of-range values with probability ~1.
__global__ void k_detect(const void* ei) {
    const long long* p = (const long long*)ei;
    long long v = p[threadIdx.x];         // 2 KB read, in bounds either way
    if (v < 0 || v >= NN) atomicAnd(&g_is64, 0);
}

__global__ void k_degree(const void* __restrict__ ei) {
    int e = blockIdx.x * blockDim.x + threadIdx.x;
    if (e < NE) {
        int t = ld_idx(ei, (long long)NE + e);
        atomicAdd(&g_deg[t], 1.0f);
    }
}

__global__ void k_prep1(const float* __restrict__ x) {
    int i = blockIdx.x * blockDim.x + threadIdx.x;
    if (i >= NN) return;
    float d = rsqrtf(g_deg[i]);           // deg >= 1 always (self loop)
    g_dinv[i] = d;
    float2 xv = ((const float2*)x)[i];
    float2 q = make_float2(d * xv.x, d * xv.y);
    g_q1[i] = q;
    g_S1[i] = q;                          // self-loop contribution
}

__global__ void k_edge1(const void* __restrict__ ei) {
    int e = blockIdx.x * blockDim.x + threadIdx.x;
    if (e >= NE) return;
    int s = ld_idx(ei, e);
    int t = ld_idx(ei, (long long)NE + e);
    float2 v = g_q1[s];
    atomicAdd(&g_S1[t], v);               // red.global.v2.f32 (sm_90+)
}

__global__ void k_mid(const float* __restrict__ W1, const float* __restrict__ b1) {
    int i = blockIdx.x * blockDim.x + threadIdx.x;
    if (i >= NN) return;
    float d = g_dinv[i];
    float2 Sv = g_S1[i];
    float yx = d * Sv.x;
    float yy = d * Sv.y;
    __half2 h2[8];
#pragma unroll
    for (int c = 0; c < 4; c++) {
        float4 w0 = ((const float4*)W1)[c];          // W1 row 0
        float4 w1 = ((const float4*)(W1 + 16))[c];   // W1 row 1
        float4 bb = ((const float4*)b1)[c];
        float hx = d * fmaxf(fmaf(yx, w0.x, fmaf(yy, w1.x, bb.x)), 0.0f);
        float hy = d * fmaxf(fmaf(yx, w0.y, fmaf(yy, w1.y, bb.y)), 0.0f);
        float hz = d * fmaxf(fmaf(yx, w0.z, fmaf(yy, w1.z, bb.z)), 0.0f);
        float hw = d * fmaxf(fmaf(yx, w0.w, fmaf(yy, w1.w, bb.w)), 0.0f);
        h2[2 * c + 0] = __floats2half2_rn(hx, hy);
        h2[2 * c + 1] = __floats2half2_rn(hz, hw);
    }
    uint4* pq = (uint4*)h2;
    g_q2h[i * 2 + 0] = pq[0];
    g_q2h[i * 2 + 1] = pq[1];
    g_S2h[i * 2 + 0] = pq[0];             // self loop
    g_S2h[i * 2 + 1] = pq[1];
}

// 2 threads per edge: each handles 8 fp16 features (16 B) -> one 128-bit load
// + one red.global.add.noftz.v4.f16x2 (16 B vector reduction, sm_90+).
__global__ void k_edge2(const void* __restrict__ ei) {
    long long tid = (long long)blockIdx.x * blockDim.x + threadIdx.x;
    long long e = tid >> 1;
    int p = (int)(tid & 1);
    if (e >= NE) return;
    int s = ld_idx(ei, e);
    int t = ld_idx(ei, (long long)NE + e);
    uint4 v = g_q2h[(long long)s * 2 + p];
    uint4* dst = &g_S2h[(long long)t * 2 + p];
    asm volatile("red.global.add.noftz.v4.f16x2 [%0], {%1,%2,%3,%4};"
                 :: "l"(dst), "r"(v.x), "r"(v.y), "r"(v.z), "r"(v.w)
                 : "memory");
}

__global__ void k_pool(const void* __restrict__ batch,
                       const float* __restrict__ W2, const float* __restrict__ b2,
                       const float* __restrict__ Wl) {
    __shared__ float sW2[16 * 32];
    __shared__ float sb2[32];
    __shared__ float sWl[32];
    for (int j = threadIdx.x; j < 512; j += blockDim.x) sW2[j] = W2[j];
    if (threadIdx.x < 32) { sb2[threadIdx.x] = b2[threadIdx.x]; sWl[threadIdx.x] = Wl[threadIdx.x]; }
    __syncthreads();

    int i = blockIdx.x * blockDim.x + threadIdx.x;
    float val = 0.0f;
    int g = -1;
    if (i < NN) {
        float d = g_dinv[i];
        uint4 a = g_S2h[i * 2 + 0];
        uint4 b = g_S2h[i * 2 + 1];
        float z[16];
        const __half2* ah = (const __half2*)&a;
        const __half2* bh = (const __half2*)&b;
#pragma unroll
        for (int j = 0; j < 4; j++) {
            float2 f = __half22float2(ah[j]);
            z[2 * j + 0] = d * f.x;
            z[2 * j + 1] = d * f.y;
            float2 f2 = __half22float2(bh[j]);
            z[8 + 2 * j + 0] = d * f2.x;
            z[8 + 2 * j + 1] = d * f2.y;
        }
        float s = 0.0f;
#pragma unroll
        for (int k = 0; k < 32; k++) {
            float acc = sb2[k];
#pragma unroll
            for (int j = 0; j < 16; j++) acc = fmaf(z[j], sW2[j * 32 + k], acc);
            s = fmaf(fmaxf(acc, 0.0f), sWl[k], s);
        }
        val = s;
        g = ld_idx(batch, i);
    }

    // batch is sorted -> contiguous equal-g runs. Segmented warp reduction to
    // avoid ~500k same-address global atomics.
    float cnt = (g >= 0) ? 1.0f : 0.0f;
    const unsigned full = 0xffffffffu;
    int lane = threadIdx.x & 31;
#pragma unroll
    for (int off = 1; off < 32; off <<= 1) {
        float vo = __shfl_down_sync(full, val, off);
        float co = __shfl_down_sync(full, cnt, off);
        int   go = __shfl_down_sync(full, g,   off);
        if (lane + off < 32 && go == g) { val += vo; cnt += co; }
    }
    int gup = __shfl_up_sync(full, g, 1);
    if (g >= 0 && (lane == 0 || gup != g)) {
        atomicAdd(&g_psum[g], val);
        atomicAdd(&g_pcnt[g], cnt);
    }
}

__global__ void k_out(float* __restrict__ out, const float* __restrict__ bl) {
    int g = blockIdx.x * blockDim.x + threadIdx.x;
    if (g < NG) out[g] = g_psum[g] / fmaxf(g_pcnt[g], 1.0f) + bl[0];
}

extern "C" void kernel_launch(void* const* d_in, const int* in_sizes, int n_in,
                              void* d_out, int out_size) {
    const float* x     = (const float*)d_in[0];
    const void*  ei    = d_in[1];
    const void*  batch = d_in[2];
    const float* W1    = (const float*)d_in[3];
    const float* b1    = (const float*)d_in[4];
    const float* W2    = (const float*)d_in[5];
    const float* b2    = (const float*)d_in[6];
    const float* Wl    = (const float*)d_in[7];
    const float* bl    = (const float*)d_in[8];
    float* out = (float*)d_out;

    const int TB = 256;
    k_init  <<<(NN + TB - 1) / TB, TB>>>();
    k_detect<<<1, 256>>>(ei);
    k_degree<<<(NE + TB - 1) / TB, TB>>>(ei);
    k_prep1 <<<(NN + TB - 1) / TB, TB>>>(x);
    k_edge1 <<<(NE + TB - 1) / TB, TB>>>(ei);
    k_mid   <<<(NN + TB - 1) / TB, TB>>>(W1, b1);
    k_edge2 <<<(int)(((long long)NE * 2 + TB - 1) / TB), TB>>>(ei);
    k_pool  <<<(NN + TB - 1) / TB, TB>>>(batch, W2, b2, Wl);
    k_out   <<<(NG + TB - 1) / TB, TB>>>(out, bl);
}

// round 4
// speedup vs baseline: 1.2566x; 1.0317x over previous
#include <cuda_runtime.h>
#include <cuda_fp16.h>

#define NN 500000
#define NE 8000000
#define NG 1024

// Scratch (static __device__ — no allocations allowed)
__device__ int    g_is64;
__device__ float  g_deg[NN];
__device__ float  g_dinv[NN];
__device__ float2 g_q1[NN];
__device__ float2 g_S1[NN];
__device__ uint4  g_q2h[NN * 2];   // 16 fp16 per node = dinv * relu(y@W1+b1), packed
__device__ uint4  g_S2h[NN * 2];   // fp16 accumulator
__device__ float  g_psum[NG];
__device__ float  g_pcnt[NG];

// Load index element i from a buffer that is either int64 or int32.
__device__ __forceinline__ int ld_idx(const void* p, long long i) {
    if (g_is64) return (int)__ldcg((const long long*)p + i);
    return __ldcg((const int*)p + i);
}

// init + dtype detect fused. Probe first 256 words as int64: node ids are in
// [0, NN), so int32 data reinterpreted as int64 is out of range w.p. ~1.
__global__ void k_init(const void* ei) {
    int i = blockIdx.x * blockDim.x + threadIdx.x;
    if (i == 0) g_is64 = 1;
    if (i < NN) g_deg[i] = 1.0f;          // self loop
    if (i < NG) { g_psum[i] = 0.0f; g_pcnt[i] = 0.0f; }
    if (blockIdx.x == 1) {                // one block probes (runs before use:
        long long v = ((const long long*)ei)[threadIdx.x]; // same-grid no, but
        if (v < 0 || v >= NN) atomicAnd(&g_is64, 0);       // see k_degree note
    }
}

// NOTE: g_is64 is produced by k_init (block 1) and consumed by later kernels
// only — k_init itself never calls ld_idx, so no intra-grid ordering issue.

__global__ void k_degree(const void* __restrict__ ei) {
    int e = blockIdx.x * blockDim.x + threadIdx.x;
    if (e < NE) {
        int t = ld_idx(ei, (long long)NE + e);
        atomicAdd(&g_deg[t], 1.0f);
    }
}

__global__ void k_prep1(const float* __restrict__ x) {
    int i = blockIdx.x * blockDim.x + threadIdx.x;
    if (i >= NN) return;
    float d = rsqrtf(g_deg[i]);           // deg >= 1 always (self loop)
    g_dinv[i] = d;
    float2 xv = ((const float2*)x)[i];
    float2 q = make_float2(d * xv.x, d * xv.y);
    g_q1[i] = q;
    g_S1[i] = q;                          // self-loop contribution
}

__global__ void k_edge1(const void* __restrict__ ei) {
    int e = blockIdx.x * blockDim.x + threadIdx.x;
    if (e >= NE) return;
    int s = ld_idx(ei, e);
    int t = ld_idx(ei, (long long)NE + e);
    float2 v = g_q1[s];
    atomicAdd(&g_S1[t], v);               // red.global.v2.f32 (sm_90+)
}

__global__ void k_mid(const float* __restrict__ W1, const float* __restrict__ b1) {
    int i = blockIdx.x * blockDim.x + threadIdx.x;
    if (i >= NN) return;
    float d = g_dinv[i];
    float2 Sv = g_S1[i];
    float yx = d * Sv.x;
    float yy = d * Sv.y;
    __half2 h2[8];
#pragma unroll
    for (int c = 0; c < 4; c++) {
        float4 w0 = ((const float4*)W1)[c];          // W1 row 0
        float4 w1 = ((const float4*)(W1 + 16))[c];   // W1 row 1
        float4 bb = ((const float4*)b1)[c];
        float hx = d * fmaxf(fmaf(yx, w0.x, fmaf(yy, w1.x, bb.x)), 0.0f);
        float hy = d * fmaxf(fmaf(yx, w0.y, fmaf(yy, w1.y, bb.y)), 0.0f);
        float hz = d * fmaxf(fmaf(yx, w0.z, fmaf(yy, w1.z, bb.z)), 0.0f);
        float hw = d * fmaxf(fmaf(yx, w0.w, fmaf(yy, w1.w, bb.w)), 0.0f);
        h2[2 * c + 0] = __floats2half2_rn(hx, hy);
        h2[2 * c + 1] = __floats2half2_rn(hz, hw);
    }
    uint4* pq = (uint4*)h2;
    g_q2h[i * 2 + 0] = pq[0];
    g_q2h[i * 2 + 1] = pq[1];
    g_S2h[i * 2 + 0] = pq[0];             // self loop
    g_S2h[i * 2 + 1] = pq[1];
}

// 2 threads per edge: each handles 8 fp16 features (16 B) -> one 128-bit load
// + one red.global.add.noftz.v4.f16x2 (16 B vector reduction, sm_90+).
__global__ void k_edge2(const void* __restrict__ ei) {
    long long tid = (long long)blockIdx.x * blockDim.x + threadIdx.x;
    long long e = tid >> 1;
    int p = (int)(tid & 1);
    if (e >= NE) return;
    int s = ld_idx(ei, e);
    int t = ld_idx(ei, (long long)NE + e);
    uint4 v = g_q2h[(long long)s * 2 + p];
    uint4* dst = &g_S2h[(long long)t * 2 + p];
    asm volatile("red.global.add.noftz.v4.f16x2 [%0], {%1,%2,%3,%4};"
                 :: "l"(dst), "r"(v.x), "r"(v.y), "r"(v.z), "r"(v.w)
                 : "memory");
}

// Packed fp32x2 FMA (Blackwell sm_100a+): d = a*b + c on two f32 lanes.
__device__ __forceinline__ unsigned long long fma_f32x2(
    unsigned long long a, unsigned long long b, unsigned long long c) {
    unsigned long long d;
    asm("fma.rn.f32x2 %0, %1, %2, %3;" : "=l"(d) : "l"(a), "l"(b), "l"(c));
    return d;
}
__device__ __forceinline__ unsigned long long pack2(float lo, float hi) {
    unsigned long long r;
    asm("mov.b64 %0, {%1, %2};" : "=l"(r) : "f"(lo), "f"(hi));
    return r;
}
__device__ __forceinline__ float2 unpack2(unsigned long long v) {
    float lo, hi;
    asm("mov.b64 {%0, %1}, %2;" : "=f"(lo), "=f"(hi) : "l"(v));
    return make_float2(lo, hi);
}

__global__ void k_pool(const void* __restrict__ batch,
                       const float* __restrict__ W2, const float* __restrict__ b2,
                       const float* __restrict__ Wl) {
    // W2 as pairs along the 32-output axis: sW2p[j][kp] = (W2[j][2kp], W2[j][2kp+1])
    __shared__ unsigned long long sW2p[16 * 16];
    __shared__ unsigned long long sb2p[16];
    __shared__ unsigned long long sWlp[16];
    for (int j = threadIdx.x; j < 256; j += blockDim.x)
        sW2p[j] = ((const unsigned long long*)W2)[j];   // same layout, pairwise
    if (threadIdx.x < 16) {
        sb2p[threadIdx.x] = ((const unsigned long long*)b2)[threadIdx.x];
        sWlp[threadIdx.x] = ((const unsigned long long*)Wl)[threadIdx.x];
    }
    __syncthreads();

    int i = blockIdx.x * blockDim.x + threadIdx.x;
    float val = 0.0f;
    int g = -1;
    if (i < NN) {
        float d = g_dinv[i];
        uint4 a = g_S2h[i * 2 + 0];
        uint4 b = g_S2h[i * 2 + 1];
        unsigned long long zz[16];        // (z[j], z[j]) broadcast pairs
        const __half2* ah = (const __half2*)&a;
        const __half2* bh = (const __half2*)&b;
#pragma unroll
        for (int j = 0; j < 4; j++) {
            float2 f = __half22float2(ah[j]);
            zz[2 * j + 0] = pack2(d * f.x, d * f.x);
            zz[2 * j + 1] = pack2(d * f.y, d * f.y);
            float2 f2 = __half22float2(bh[j]);
            zz[8 + 2 * j + 0] = pack2(d * f2.x, d * f2.x);
            zz[8 + 2 * j + 1] = pack2(d * f2.y, d * f2.y);
        }
        float s = 0.0f;
#pragma unroll
        for (int kp = 0; kp < 16; kp++) {
            unsigned long long acc = sb2p[kp];
#pragma unroll
            for (int j = 0; j < 16; j++)
                acc = fma_f32x2(zz[j], sW2p[j * 16 + kp], acc);
            float2 u = unpack2(acc);
            float2 wl = unpack2(sWlp[kp]);
            s = fmaf(fmaxf(u.x, 0.0f), wl.x, s);
            s = fmaf(fmaxf(u.y, 0.0f), wl.y, s);
        }
        val = s;
        g = g_is64 ? (int)((const long long*)batch)[i] : ((const int*)batch)[i];
    }

    // batch is sorted -> contiguous equal-g runs. Segmented warp reduction to
    // avoid ~500k same-address global atomics.
    float cnt = (g >= 0) ? 1.0f : 0.0f;
    const unsigned full = 0xffffffffu;
    int lane = threadIdx.x & 31;
#pragma unroll
    for (int off = 1; off < 32; off <<= 1) {
        float vo = __shfl_down_sync(full, val, off);
        float co = __shfl_down_sync(full, cnt, off);
        int   go = __shfl_down_sync(full, g,   off);
        if (lane + off < 32 && go == g) { val += vo; cnt += co; }
    }
    int gup = __shfl_up_sync(full, g, 1);
    if (g >= 0 && (lane == 0 || gup != g)) {
        atomicAdd(&g_psum[g], val);
        atomicAdd(&g_pcnt[g], cnt);
    }
}

__global__ void k_out(float* __restrict__ out, const float* __restrict__ bl) {
    int g = blockIdx.x * blockDim.x + threadIdx.x;
    if (g < NG) out[g] = g_psum[g] / fmaxf(g_pcnt[g], 1.0f) + bl[0];
}

extern "C" void kernel_launch(void* const* d_in, const int* in_sizes, int n_in,
                              void* d_out, int out_size) {
    const float* x     = (const float*)d_in[0];
    const void*  ei    = d_in[1];
    const void*  batch = d_in[2];
    const float* W1    = (const float*)d_in[3];
    const float* b1    = (const float*)d_in[4];
    const float* W2    = (const float*)d_in[5];
    const float* b2    = (const float*)d_in[6];
    const float* Wl    = (const float*)d_in[7];
    const float* bl    = (const float*)d_in[8];
    float* out = (float*)d_out;

    const int TB = 256;
    k_init  <<<(NN + TB - 1) / TB, TB>>>(ei);
    k_degree<<<(NE + TB - 1) / TB, TB>>>(ei);
    k_prep1 <<<(NN + TB - 1) / TB, TB>>>(x);
    k_edge1 <<<(NE + TB - 1) / TB, TB>>>(ei);
    k_mid   <<<(NN + TB - 1) / TB, TB>>>(W1, b1);
    k_edge2 <<<(int)(((long long)NE * 2 + TB - 1) / TB), TB>>>(ei);
    k_pool  <<<(NN + TB - 1) / TB, TB>>>(batch, W2, b2, Wl);
    k_out   <<<(NG + TB - 1) / TB, TB>>>(out, bl);
}